// round 16
// baseline (speedup 1.0000x reference)
#include <cuda_runtime.h>
#include <cuda_fp16.h>
#include <math.h>
#include <stdint.h>

#define NT   4096      // trees
#define KC   16        // children
#define DM   256       // DOUT
#define GD   1024      // 4*DOUT
#define NCMB 5         // recurrent combos: (j0,f),(j0,b),(j1,f),(j2,f),(j3,f)
#define NCTA 296       // persistent grid: 2 CTAs x 148 SMs

// ---------------- scratch (device globals; no allocations allowed) ----------
__device__ __align__(16) __half s_x16   [(long)NT*DM];
__device__ __align__(16) __half s_xseq16[(long)NT*KC*DM];   // k-major: [k*NT+n][DM]
__device__ __align__(16) __half s_xlast16[(long)NT*DM];
__device__ __align__(16) __half s_Wih5h [(long)NCMB*GD*DM]; // gate-interleaved
__device__ __align__(16) __half s_Whh5h [(long)NCMB*GD*DM]; // gate-interleaved
__device__ __align__(16) __half s_WihBh [3L*GD*DM];         // gate-interleaved
__device__ __align__(16) __half s_Wwh   [(long)GD*DM];
__device__ __align__(16) __half s_fch   [4L*DM*2*DM];
__device__ __align__(16) __half s_h16   [2L*NCMB*NT*DM];    // double-buffered
__device__ __align__(16) __half s_ycat016[(long)NT*KC*2*DM]; // k-major rows
__device__ __align__(16) __half s_ylcat16[3L*NT*2*DM];
__device__ __align__(16) __half s_ys016 [(long)NT*KC*DM];
__device__ __align__(16) __half s_ysl16 [3L*NT*DM];
__device__ float s_cseq [(long)NT*KC*DM];
__device__ int   s_len  [NT];        // sorted (descending)
__device__ int   s_ord  [NT];
__device__ int   s_lenOrig[NT];
__device__ int   s_cntF [17];        // cntF[s] = #trees with len > s
__device__ float s_b5   [NCMB*GD];   // gate-interleaved
__device__ float s_hb   [3*GD];      // gate-interleaved
__device__ float s_c    [(long)NCMB*NT*DM];
__device__ float s_Wx   [(long)NT*GD];
// dependency-queue state (reset each launch in sort_k)
__device__ int s_tileBase[16*NCMB+1];  // cumulative rec tiles per (s,c)
__device__ int s_tileSC [16*NCMB*32*8]; // tile -> segment index (flat decode)
__device__ int s_firstStepB[32];       // bwd combo: first active step per rowTile
__device__ int s_dep[NCMB*32];         // completed col-tiles per (combo,rowTile)
__device__ int g_qHead;

__device__ __forceinline__ float sigf(float x){ return 1.f/(1.f+expf(-x)); }

__device__ __forceinline__ void mma_f16(float4& c,
        uint32_t a0, uint32_t a1, uint32_t a2, uint32_t a3,
        uint32_t b0, uint32_t b1){
    asm volatile(
        "mma.sync.aligned.m16n8k16.row.col.f32.f16.f16.f32 "
        "{%0,%1,%2,%3}, {%4,%5,%6,%7}, {%8,%9}, {%0,%1,%2,%3};"
        : "+f"(c.x), "+f"(c.y), "+f"(c.z), "+f"(c.w)
        : "r"(a0), "r"(a1), "r"(a2), "r"(a3), "r"(b0), "r"(b1));
}

__device__ __forceinline__ void ldsm_x4(uint32_t& r0, uint32_t& r1,
                                        uint32_t& r2, uint32_t& r3, uint32_t addr){
    asm volatile("ldmatrix.sync.aligned.m8n8.x4.shared.b16 {%0,%1,%2,%3}, [%4];"
                 : "=r"(r0),"=r"(r1),"=r"(r2),"=r"(r3) : "r"(addr));
}
__device__ __forceinline__ void ldsm_x2(uint32_t& r0, uint32_t& r1, uint32_t addr){
    asm volatile("ldmatrix.sync.aligned.m8n8.x2.shared.b16 {%0,%1}, [%2];"
                 : "=r"(r0),"=r"(r1) : "r"(addr));
}

// ---------------- sort + queue-table build -----------------------------------
__global__ void sort_k(const int* __restrict__ indice){
    __shared__ int hist[17];
    __shared__ int binCur[17];
    int tid = threadIdx.x;
    if (tid < 17) hist[tid]=0;
    __syncthreads();
    for (int n=tid; n<NT; n+=blockDim.x){
        int l=0;
        #pragma unroll
        for (int k=0;k<KC;k++) if (indice[n*KC+k]!=-1) l++;
        s_lenOrig[n]=l;
        atomicAdd(&hist[l],1);
    }
    __syncthreads();
    if (tid==0){
        int run=0;
        for (int l=16;l>=1;l--){ binCur[l]=run; run+=hist[l]; }
        int c=0;
        s_cntF[16]=0;
        for (int s=15;s>=0;s--){ c += hist[s+1]; s_cntF[s]=c; }
        g_qHead = 0;
        int tb=0; s_tileBase[0]=0;
        for (int i=0;i<16*NCMB;i++){
            int s=i/NCMB, cc=i%NCMB;
            int lim = (cc==1)? s_cntF[15-s] : s_cntF[s];
            tb += ((lim+127)>>7)<<3;
            s_tileBase[i+1]=tb;
        }
        for (int r=0;r<32;r++){
            int fs=16;
            for (int s=0;s<16;s++) if (s_cntF[15-s] > 128*r){ fs=s; break; }
            s_firstStepB[r]=fs;
        }
    }
    if (tid < NCMB*32) s_dep[tid]=0;
    __syncthreads();
    for (int i=0; i<16*NCMB; i++){
        int b0 = s_tileBase[i], b1 = s_tileBase[i+1];
        for (int t = b0 + tid; t < b1; t += blockDim.x) s_tileSC[t] = i;
    }
    for (int n=tid; n<NT; n+=blockDim.x){
        int l=s_lenOrig[n];
        int pos=atomicAdd(&binCur[l],1);
        s_ord[pos]=n;
        s_len[pos]=l;
    }
}

// ---------------- prep: pack + convert weights (gate-interleaved) -----------
__global__ void prep_weights(const float* __restrict__ Wih, const float* __restrict__ Whh,
                             const float* __restrict__ bih, const float* __restrict__ bhh,
                             const float* __restrict__ W_w, const float* __restrict__ fc,
                             const float* __restrict__ h0){
    const int map5[5]={0,1,2,4,6};
    const int mapB[3]={3,5,7};
    long idx = (long)blockIdx.x*blockDim.x + threadIdx.x;
    long stride = (long)gridDim.x*blockDim.x;
    for (long i=idx; i<(long)NCMB*GD*DM; i+=stride){
        int cmb = (int)(i/((long)GD*DM)); long rem = i%((long)GD*DM);
        int rp = (int)(rem/DM); int kcol = (int)(rem%DM);
        int q = (rp>>5)&3; int du = ((rp>>7)<<5)|(rp&31);
        long src = (long)map5[cmb]*GD*DM + (long)(q*256+du)*DM + kcol;
        s_Wih5h[i]=__float2half(Wih[src]);
        s_Whh5h[i]=__float2half(Whh[src]);
    }
    for (long i=idx; i<3L*GD*DM; i+=stride){
        int jb = (int)(i/((long)GD*DM)); long rem = i%((long)GD*DM);
        int rp = (int)(rem/DM); int kcol = (int)(rem%DM);
        int q = (rp>>5)&3; int du = ((rp>>7)<<5)|(rp&31);
        s_WihBh[i]=__float2half(Wih[(long)mapB[jb]*GD*DM + (long)(q*256+du)*DM + kcol]);
    }
    for (long i=idx; i<(long)GD*DM; i+=stride)
        s_Wwh[i]=__float2half(W_w[i]);
    for (long i=idx; i<4L*DM*2*DM; i+=stride)
        s_fch[i]=__float2half(fc[i]);
    for (long i=idx; i<(long)NCMB*GD; i+=stride){
        int cmb=(int)(i/GD); int rp=(int)(i%GD);
        int q=(rp>>5)&3; int du=((rp>>7)<<5)|(rp&31);
        int r = q*256+du;
        s_b5[i]=bih[map5[cmb]*GD+r]+bhh[map5[cmb]*GD+r];
    }
    for (long i=idx; i<3L*GD; i+=stride){
        int jb=(int)(i/GD); int rp=(int)(i%GD);
        int q=(rp>>5)&3; int du=((rp>>7)<<5)|(rp&31);
        int r=q*256+du;
        int jd2=2*(jb+1)+1;
        const float* w = Whh + (long)jd2*GD*DM + (long)r*DM;
        const float* h = h0 + (jb+1)*DM;
        float acc=0.f;
        #pragma unroll 8
        for (int d=0; d<DM; d++) acc += h[d]*w[d];
        s_hb[i] = acc + bih[jd2*GD+r] + bhh[jd2*GD+r];
    }
}

// ------ gather (active children) + x conv + h/c init, one kernel -------------
__global__ void gather_k(const float* __restrict__ h_tensor,
                         const float* __restrict__ c_tensor,
                         const int*   __restrict__ indice,
                         const float* __restrict__ x,
                         const float* __restrict__ h0, const float* __restrict__ c0){
    long idx = (long)blockIdx.x*blockDim.x + threadIdx.x;
    long gsz = (long)gridDim.x*blockDim.x;
    const int jmap[5]={0,0,1,2,3};

    for (long i=idx; i<(long)NT*(DM/4); i+=gsz){
        int sn = (int)(i/(DM/4)); int d4 = (int)(i%(DM/4));
        int orig = s_ord[sn];
        float4 v = ((const float4*)x)[(long)orig*(DM/4)+d4];
        ((__half2*)s_x16)[((long)sn*DM + d4*4)>>1]     = __floats2half2_rn(v.x, v.y);
        ((__half2*)s_x16)[(((long)sn*DM + d4*4)>>1)+1] = __floats2half2_rn(v.z, v.w);
    }
    for (long i=idx; i<(long)NCMB*NT*(DM/2); i+=gsz){
        int cmb = (int)((i/((long)NT*(DM/2)))%NCMB);
        int d2 = (int)(i%(DM/2));
        __half2 v = __floats2half2_rn(h0[jmap[cmb]*DM+2*d2], h0[jmap[cmb]*DM+2*d2+1]);
        ((__half2*)s_h16)[i] = v;
        ((__half2*)s_h16)[i + (long)NCMB*NT*(DM/2)] = v;
    }
    for (long i=idx; i<(long)NCMB*NT*(DM/2); i+=gsz){
        int cmb = (int)(i/((long)NT*(DM/2)));
        int d2 = (int)(i%(DM/2));
        ((float2*)s_c)[i] = make_float2(c0[jmap[cmb]*DM+2*d2], c0[jmap[cmb]*DM+2*d2+1]);
    }
    for (long i=idx; i<(long)NT*KC*(DM/4); i+=gsz){
        long nk = i / (DM/4);
        int  d4 = (int)(i % (DM/4));
        int sn = (int)(nk >> 4); int k = (int)(nk & 15);
        int len = s_len[sn];
        if (k >= len) continue;
        int orig = s_ord[sn];
        int id = indice[orig*KC+k];
        float4 h = ((const float4*)h_tensor)[(long)id*(DM/4)+d4];
        ((float4*)s_cseq)[((long)sn*KC+k)*(DM/4)+d4] = ((const float4*)c_tensor)[(long)id*(DM/4)+d4];
        __half2 h01 = __floats2half2_rn(h.x, h.y);
        __half2 h23 = __floats2half2_rn(h.z, h.w);
        long xo = ((long)k*NT + sn)*DM + d4*4;
        ((__half2*)s_xseq16)[xo>>1]     = h01;
        ((__half2*)s_xseq16)[(xo>>1)+1] = h23;
        if (k == len-1){
            long lo = (long)sn*DM + d4*4;
            ((__half2*)s_xlast16)[lo>>1]     = h01;
            ((__half2*)s_xlast16)[(lo>>1)+1] = h23;
        }
    }
}

// ---------------- shared GEMM plumbing (32-wide chunks, gemm_h) ---------------
#define STR2 20                       // u32 per smem row (16 data + 4 pad)
#define AB_U32 (128*STR2)
#define ABUF(b) ((b)*AB_U32)
#define BBUF(b) (3*AB_U32 + (b)*AB_U32)
#define SMEM_SZ (6*AB_U32*4)          // 61440 bytes

// rec_k: 64-wide chunks (128B rows)
#define STR3 36                       // u32 per smem row (32 data + 4 pad)
#define AB3_U32 (128*STR3)
#define A3BUF(b) ((b)*AB3_U32)
#define B3BUF(b) (3*AB3_U32 + (b)*AB3_U32)
#define SMEM_R (6*AB3_U32*4)          // 110592 bytes

#define LDSM_OFFS(aoff, boff, STRX)                                               \
    int aoff[4], boff[4];                                                         \
    {                                                                             \
        int rA = lane & 15;                                                       \
        int cA = (lane >> 4) << 2;                                                \
        _Pragma("unroll")                                                         \
        for (int mt=0; mt<4; mt++)                                                \
            aoff[mt] = ((wrw*64 + mt*16 + rA)*(STRX) + cA)*4;                     \
        int rB = lane & 7;                                                        \
        int cB = ((lane >> 3) & 1) << 2;                                          \
        _Pragma("unroll")                                                         \
        for (int nt=0; nt<4; nt++)                                                \
            boff[nt] = ((wcw*32 + nt*8 + rB)*(STRX) + cB)*4;                      \
    }

#define PRE16(Ab, Bb, Astride, Bstride, brow_, bcol_, kb_, buf) do {              \
    long kb = (kb_);                                                              \
    _Pragma("unroll")                                                             \
    for (int l=0;l<2;l++){                                                        \
        int r = lrow4 + l*64;                                                     \
        uint32_t da = sbase + (ABUF(buf) + r*STR2)*4 + lq*16;                     \
        asm volatile("cp.async.cg.shared.global [%0],[%1],16;"                    \
                     :: "r"(da), "l"((Ab) + ((brow_)+r)*(Astride) + kb + lq*8));  \
        uint32_t db = sbase + (BBUF(buf) + r*STR2)*4 + lq*16;                     \
        asm volatile("cp.async.cg.shared.global [%0],[%1],16;"                    \
                     :: "r"(db), "l"((Bb) + ((bcol_) + r)*(Bstride) + kb + lq*8)); \
    }                                                                             \
    asm volatile("cp.async.commit_group;");                                       \
} while(0)

// 64-wide prefetch: 128 rows x 128B per matrix; thread -> row tid>>1, 64B half
#define PRE64(Ab, Bb, Astride, brow_, bcol_, kb_, buf) do {                       \
    long kb = (kb_);                                                              \
    int r2 = tid >> 1;                                                            \
    int hh = (tid & 1) * 16;            /* u32 offset in 32-u32 row */            \
    _Pragma("unroll")                                                             \
    for (int j=0;j<4;j++){                                                        \
        uint32_t da = sbase + (A3BUF(buf) + r2*STR3 + hh + j*4)*4;                \
        asm volatile("cp.async.cg.shared.global [%0],[%1],16;"                    \
             :: "r"(da), "l"((Ab) + ((brow_)+r2)*(Astride) + kb + (hh+j*4)*2));   \
        uint32_t db = sbase + (B3BUF(buf) + r2*STR3 + hh + j*4)*4;                \
        asm volatile("cp.async.cg.shared.global [%0],[%1],16;"                    \
             :: "r"(db), "l"((Bb) + ((bcol_)+r2)*(Astride) + kb + (hh+j*4)*2));   \
    }                                                                             \
    asm volatile("cp.async.commit_group;");                                       \
} while(0)

#define MMA_BODY(af, bf)                                                          \
    _Pragma("unroll")                                                             \
    for (int mt=0; mt<4; mt++)                                                    \
        _Pragma("unroll")                                                         \
        for (int nt=0; nt<4; nt++)                                                \
            mma_f16(acc[mt][nt], af[0],af[1],af[2],af[3], bf##0, bf##1);

#define MAINLOOP_CHUNK(cb)  do {                                                  \
    uint32_t baA = sbase + (ABUF(cb))*4;                                          \
    uint32_t baB = sbase + (BBUF(cb))*4;                                          \
    _Pragma("unroll")                                                             \
    for (int ks = 0; ks < 2; ks++){                                               \
        uint32_t af[4][4], bf[4][2];                                              \
        _Pragma("unroll")                                                         \
        for (int mt=0; mt<4; mt++)                                                \
            ldsm_x4(af[mt][0],af[mt][1],af[mt][2],af[mt][3],                      \
                    baA + ks*32 + aoff[mt]);                                      \
        _Pragma("unroll")                                                         \
        for (int nt=0; nt<4; nt++)                                                \
            ldsm_x2(bf[nt][0],bf[nt][1], baB + ks*32 + boff[nt]);                 \
        _Pragma("unroll")                                                         \
        for (int mt=0; mt<4; mt++)                                                \
            _Pragma("unroll")                                                     \
            for (int nt=0; nt<4; nt++)                                            \
                mma_f16(acc[mt][nt], af[mt][0],af[mt][1],af[mt][2],af[mt][3],     \
                        bf[nt][0], bf[nt][1]);                                    \
    }                                                                             \
} while(0)

#define MAINLOOP64(cb)  do {                                                      \
    uint32_t baA = sbase + (A3BUF(cb))*4;                                         \
    uint32_t baB = sbase + (B3BUF(cb))*4;                                         \
    _Pragma("unroll")                                                             \
    for (int ks = 0; ks < 4; ks++){                                               \
        uint32_t af[4][4], bf[4][2];                                              \
        _Pragma("unroll")                                                         \
        for (int mt=0; mt<4; mt++)                                                \
            ldsm_x4(af[mt][0],af[mt][1],af[mt][2],af[mt][3],                      \
                    baA + ks*32 + aoff3[mt]);                                     \
        _Pragma("unroll")                                                         \
        for (int nt=0; nt<4; nt++)                                                \
            ldsm_x2(bf[nt][0],bf[nt][1], baB + ks*32 + boff3[nt]);                \
        _Pragma("unroll")                                                         \
        for (int mt=0; mt<4; mt++)                                                \
            _Pragma("unroll")                                                     \
            for (int nt=0; nt<4; nt++)                                            \
                mma_f16(acc[mt][nt], af[mt][0],af[mt][1],af[mt][2],af[mt][3],     \
                        bf[nt][0], bf[nt][1]);                                    \
    }                                                                             \
} while(0)

// ---------------- generic fp16 GEMM (non-recurrent launches) -----------------
__global__ void __launch_bounds__(256,2) gemm_h(
    const __half* __restrict__ A, long aBatch,
    const __half* __restrict__ B, long bBatch,
    const float* __restrict__ bias, long biasBatch,
    float* __restrict__ CF, __half* __restrict__ CH, long cBatch, int cRow,
    int M, int N, int K,
    const int* __restrict__ exCnt, int exitKind,
    const float* __restrict__ fuseC0)
{
    int z = blockIdx.z;
    long brow = (long)blockIdx.y * 128;
    if (exitKind == 1){
        int k = (int)(brow >> 12);
        int w = (int)(brow & 4095);
        if (w >= exCnt[k]) return;
    }
    extern __shared__ uint32_t sm[];
    uint32_t sbase;
    asm("{ .reg .u64 t; cvta.to.shared.u64 t, %1; cvt.u32.u64 %0, t; }"
        : "=r"(sbase) : "l"(sm));
    int tid = threadIdx.x;
    int wid = tid >> 5, lane = tid & 31;
    int gq = lane >> 2, tq = lane & 3;
    int wrw = wid >> 2, wcw = wid & 3;
    int lrow4 = tid >> 2, lq = tid & 3;
    LDSM_OFFS(aoff, boff, STR2);

    const __half* Ab = A + (long)z*aBatch;
    const __half* Bb = B + (long)z*bBatch;
    long bcol = (long)blockIdx.x * 128;

    float4 acc[4][4];
    #pragma unroll
    for (int i=0;i<4;i++)
        #pragma unroll
        for (int j=0;j<4;j++) acc[i][j] = make_float4(0.f,0.f,0.f,0.f);

    int nCh = K >> 5;
    PRE16(Ab, Bb, K, K, brow, bcol, 0L, 0);
    if (nCh > 1) PRE16(Ab, Bb, K, K, brow, bcol, 32L, 1);
    for (int i = 0; i < nCh; i++){
        if (i + 1 < nCh) asm volatile("cp.async.wait_group 1;" ::: "memory");
        else             asm volatile("cp.async.wait_group 0;" ::: "memory");
        __syncthreads();
        MAINLOOP_CHUNK(i % 3);
        if (i + 2 < nCh){
            PRE16(Ab, Bb, K, K, brow, bcol, (long)(i+2)*32, (i + 2) % 3);
        }
    }

    const float* biasb = bias ? bias + (long)z*biasBatch : (const float*)0;

    if (fuseC0){
        __half* gs = (__half*)sm;
        __syncthreads();
        #pragma unroll
        for (int mt=0; mt<4; mt++){
            int lr0 = wrw*64 + mt*16 + gq;
            #pragma unroll
            for (int nt=0; nt<4; nt++){
                int lcol = wcw*32 + nt*8 + 2*tq;
                long col2 = bcol + lcol;
                float b0 = biasb[col2], b1 = biasb[col2+1];
                *reinterpret_cast<__half2*>(&gs[lr0*132 + lcol]) =
                    __floats2half2_rn(acc[mt][nt].x + b0, acc[mt][nt].y + b1);
                *reinterpret_cast<__half2*>(&gs[(lr0+8)*132 + lcol]) =
                    __floats2half2_rn(acc[mt][nt].z + b0, acc[mt][nt].w + b1);
            }
        }
        __syncthreads();
        int colTile = blockIdx.x;
        #pragma unroll
        for (int it=0; it<8; it++){
            int idx2 = tid + it*256;
            int row = idx2 >> 4, up = idx2 & 15;
            int u = up*2;
            int n = (int)brow + row;
            int d = (colTile<<5) + u;
            float2 gi = __half22float2(*reinterpret_cast<const __half2*>(&gs[row*132 + u]));
            float2 gf = __half22float2(*reinterpret_cast<const __half2*>(&gs[row*132 + 32 + u]));
            float2 gu = __half22float2(*reinterpret_cast<const __half2*>(&gs[row*132 + 64 + u]));
            float2 go = __half22float2(*reinterpret_cast<const __half2*>(&gs[row*132 + 96 + u]));
            float2 cp = *reinterpret_cast<const float2*>(&fuseC0[(z+1)*DM + d]);
            float cnx = sigf(gf.x)*cp.x + sigf(gi.x)*tanhf(gu.x);
            float cny = sigf(gf.y)*cp.y + sigf(gi.y)*tanhf(gu.y);
            float hnx = sigf(go.x)*tanhf(cnx);
            float hny = sigf(go.y)*tanhf(cny);
            *reinterpret_cast<__half2*>(&s_ylcat16[((long)z*NT+n)*(2*DM) + DM + d]) =
                __floats2half2_rn(hnx, hny);
        }
        return;
    }

    #pragma unroll
    for (int mt=0; mt<4; mt++){
        long row0 = brow + wrw*64 + mt*16 + gq;
        #pragma unroll
        for (int nt=0; nt<4; nt++){
            long col = bcol + wcw*32 + nt*8 + 2*tq;
            float2 v0 = make_float2(acc[mt][nt].x, acc[mt][nt].y);
            float2 v1 = make_float2(acc[mt][nt].z, acc[mt][nt].w);
            if (biasb){
                v0.x += biasb[col];   v0.y += biasb[col+1];
                v1.x += biasb[col];   v1.y += biasb[col+1];
            }
            if (CH){
                __half* Cb = CH + (long)z*cBatch;
                *reinterpret_cast<__half2*>(&Cb[row0*cRow + col])     = __floats2half2_rn(v0.x, v0.y);
                *reinterpret_cast<__half2*>(&Cb[(row0+8)*cRow + col]) = __floats2half2_rn(v1.x, v1.y);
            } else {
                float* Cb = CF + (long)z*cBatch;
                *reinterpret_cast<float2*>(&Cb[row0*cRow + col])     = v0;
                *reinterpret_cast<float2*>(&Cb[(row0+8)*cRow + col]) = v1;
            }
        }
    }
}

// -------- persistent recurrence: work queue + 64-wide K chunks ----------------
__global__ void __launch_bounds__(256,2) rec_k(){
    extern __shared__ uint32_t sm[];
    __half* gs = (__half*)sm;          // 128 x 132 fp16 staging
    __shared__ int sh4[4];             // decoded (s,c,r,col)
    uint32_t sbase;
    asm("{ .reg .u64 t; cvta.to.shared.u64 t, %1; cvt.u32.u64 %0, t; }"
        : "=r"(sbase) : "l"(sm));
    int tid = threadIdx.x;
    int wid = tid >> 5, lane = tid & 31;
    int gq = lane >> 2, tq = lane & 3;
    int wrw = wid >> 2, wcw = wid & 3;
    LDSM_OFFS(aoff3, boff3, STR3);

    int total = s_tileBase[16*NCMB];

    while (true){
        if (tid == 0){
            int t = atomicAdd(&g_qHead, 1);
            int ss=-1, cc=0, rr=0, col=0;
            if (t < total){
                int i = s_tileSC[t];                 // flat decode: 1 load
                ss = i/NCMB; cc = i%NCMB;
                int off = t - s_tileBase[i];
                rr = off >> 3; col = off & 7;
                int first = (cc==1) ? s_firstStepB[rr] : 0;
                int need = 8*(ss - first);
                if (need > 0){
                    while (atomicAdd(&s_dep[cc*32+rr], 0) < need) __nanosleep(64);
                }
                __threadfence();   // acquire: order dep-read before h reads
            }
            sh4[0]=ss; sh4[1]=cc; sh4[2]=rr; sh4[3]=col;
        }
        __syncthreads();
        int s = sh4[0];
        if (s < 0) break;
        int c = sh4[1], rowTile = sh4[2], colTile = sh4[3];
        __syncthreads();            // sh4 consumed before next overwrite

        int rdb = s & 1, wrb = rdb ^ 1;
        int lim = (c==1) ? s_cntF[15-s] : s_cntF[s];
        long brow = (long)rowTile << 7;
        long bcol = (long)colTile << 7;
        const __half* Ah = s_h16 + ((long)rdb*NCMB + c)*NT*DM;
        const __half* Bh = s_Whh5h + (long)c*GD*DM;
        int kx = (c==1) ? 15-s : s;
        const __half* Ax = s_xseq16 + (long)kx*NT*DM;
        const __half* Bx = s_Wih5h + (long)c*GD*DM;
        const float* biasb = s_b5 + c*GD;

        float4 acc[4][4];
        #pragma unroll
        for (int i=0;i<4;i++)
            #pragma unroll
            for (int j=0;j<4;j++) acc[i][j] = make_float4(0.f,0.f,0.f,0.f);

        // 8 K-chunks of 64: 0-3 = h@Whh, 4-7 = xseq[kx]@Wih
        #define PRER(ch, buf) do {                                            \
            if ((ch) < 4) PRE64(Ah, Bh, DM, brow, bcol, (long)(ch)*64, buf);  \
            else          PRE64(Ax, Bx, DM, brow, bcol, (long)((ch)-4)*64, buf); \
        } while(0)

        PRER(0, 0);
        PRER(1, 1);
        #pragma unroll
        for (int i = 0; i < 8; i++){
            if (i < 7) asm volatile("cp.async.wait_group 1;" ::: "memory");
            else       asm volatile("cp.async.wait_group 0;" ::: "memory");
            __syncthreads();
            MAINLOOP64(i % 3);
            if (i + 2 < 8) PRER(i + 2, (i + 2) % 3);
        }
        #undef PRER
        __syncthreads();   // ring smem free before gs staging

        #pragma unroll
        for (int mt=0; mt<4; mt++){
            int lr0 = wrw*64 + mt*16 + gq;
            #pragma unroll
            for (int nt=0; nt<4; nt++){
                int lcol = wcw*32 + nt*8 + 2*tq;
                long col2 = bcol + lcol;
                float b0 = biasb[col2], b1 = biasb[col2+1];
                *reinterpret_cast<__half2*>(&gs[lr0*132 + lcol]) =
                    __floats2half2_rn(acc[mt][nt].x + b0, acc[mt][nt].y + b1);
                *reinterpret_cast<__half2*>(&gs[(lr0+8)*132 + lcol]) =
                    __floats2half2_rn(acc[mt][nt].z + b0, acc[mt][nt].w + b1);
            }
        }
        __syncthreads();

        #pragma unroll
        for (int it=0; it<8; it++){
            int idx2 = tid + it*256;
            int row = idx2 >> 4, up = idx2 & 15;
            int u = up*2;
            int n = (int)brow + row;
            if (n >= lim) continue;
            int d = (colTile<<5) + u;
            float2 gi = __half22float2(*reinterpret_cast<const __half2*>(&gs[row*132 + u]));
            float2 gf = __half22float2(*reinterpret_cast<const __half2*>(&gs[row*132 + 32 + u]));
            float2 gu = __half22float2(*reinterpret_cast<const __half2*>(&gs[row*132 + 64 + u]));
            float2 go = __half22float2(*reinterpret_cast<const __half2*>(&gs[row*132 + 96 + u]));
            long ist = ((long)c*NT + n)*DM + d;
            float2 cp = *reinterpret_cast<const float2*>(&s_c[ist]);
            float2 cn, hn;
            cn.x = sigf(gf.x)*cp.x + sigf(gi.x)*tanhf(gu.x);
            cn.y = sigf(gf.y)*cp.y + sigf(gi.y)*tanhf(gu.y);
            hn.x = sigf(go.x)*tanhf(cn.x);
            hn.y = sigf(go.y)*tanhf(cn.y);
            *reinterpret_cast<float2*>(&s_c[ist]) = cn;
            __half2 hn2 = __floats2half2_rn(hn.x, hn.y);
            *reinterpret_cast<__half2*>(&s_h16[((long)wrb*NCMB + c)*NT*DM + (long)n*DM + d]) = hn2;
            if (c == 0)
                *reinterpret_cast<__half2*>(&s_ycat016[((long)s*NT+n)*(2*DM) + d]) = hn2;
            else if (c == 1)
                *reinterpret_cast<__half2*>(&s_ycat016[((long)(15-s)*NT+n)*(2*DM) + DM + d]) = hn2;
            else if (s == s_len[n]-1)
                *reinterpret_cast<__half2*>(&s_ylcat16[((long)(c-2)*NT+n)*(2*DM) + d]) = hn2;
        }
        __threadfence();           // publish h/c writes
        __syncthreads();
        if (tid == 0) atomicAdd(&s_dep[c*32+rowTile], 1);
    }
}

__global__ void final_k(float* __restrict__ out){
    int n = blockIdx.x, d = threadIdx.x;   // n = sorted slot
    int orig = s_ord[n];
    float wf = s_Wx[(long)n*GD + d];
    float wi = s_Wx[(long)n*GD + DM + d];
    float wu = s_Wx[(long)n*GD + 2*DM + d];
    float wo = s_Wx[(long)n*GD + 3*DM + d];
    int len = s_len[n];
    float bf = 0.f;
    for (int k=0;k<len;k++){
        float y  = __half2float(s_ys016[((long)k*NT+n)*DM + d]);
        float cc = s_cseq[((long)n*KC+k)*DM + d];
        bf += sigf(wf + y) * cc;
    }
    float bi = sigf (__half2float(s_ysl16[0L*NT*DM + (long)n*DM + d]) + wi);
    float bu = tanhf(__half2float(s_ysl16[1L*NT*DM + (long)n*DM + d]) + wu);
    float bo = sigf (__half2float(s_ysl16[2L*NT*DM + (long)n*DM + d]) + wo);
    float ncv = bi*bu + bf;
    float nhv = bo*tanhf(ncv);
    out[(long)orig*DM + d] = nhv;
    out[(long)NT*DM + (long)orig*DM + d] = ncv;
}

// =============================================================================
extern "C" void kernel_launch(void* const* d_in, const int* in_sizes, int n_in,
                              void* d_out, int out_size) {
    const float* x        = (const float*)d_in[0];
    const float* h_tensor = (const float*)d_in[1];
    const float* c_tensor = (const float*)d_in[2];
    const int*   indice   = (const int*)  d_in[3];
    const float* W_w      = (const float*)d_in[4];
    const float* W_b      = (const float*)d_in[5];
    const float* h0       = (const float*)d_in[6];
    const float* c0       = (const float*)d_in[7];
    const float* Wih      = (const float*)d_in[8];
    const float* Whh      = (const float*)d_in[9];
    const float* bih      = (const float*)d_in[10];
    const float* bhh      = (const float*)d_in[11];
    const float* fc       = (const float*)d_in[12];
    float* out = (float*)d_out;

    __half *p_x16,*p_xlast16,*p_WihBh,*p_Wwh,*p_fch,
           *p_ycat016,*p_ylcat16,*p_ys016,*p_ysl16;
    float *p_hb,*p_Wx;
    int *p_cntF;
    cudaGetSymbolAddress((void**)&p_x16,     s_x16);
    cudaGetSymbolAddress((void**)&p_xlast16, s_xlast16);
    cudaGetSymbolAddress((void**)&p_WihBh,   s_WihBh);
    cudaGetSymbolAddress((void**)&p_Wwh,     s_Wwh);
    cudaGetSymbolAddress((void**)&p_fch,     s_fch);
    cudaGetSymbolAddress((void**)&p_ycat016, s_ycat016);
    cudaGetSymbolAddress((void**)&p_ylcat16, s_ylcat16);
    cudaGetSymbolAddress((void**)&p_ys016,   s_ys016);
    cudaGetSymbolAddress((void**)&p_ysl16,   s_ysl16);
    cudaGetSymbolAddress((void**)&p_hb,      s_hb);
    cudaGetSymbolAddress((void**)&p_Wx,      s_Wx);
    cudaGetSymbolAddress((void**)&p_cntF,    s_cntF);
    (void)in_sizes; (void)n_in; (void)out_size;

    cudaFuncSetAttribute(gemm_h, cudaFuncAttributeMaxDynamicSharedMemorySize, SMEM_SZ);
    cudaFuncSetAttribute(rec_k,  cudaFuncAttributeMaxDynamicSharedMemorySize, SMEM_R);

    // 1) sort + queue tables, pack/convert weights (+hb), init+gather (merged)
    sort_k<<<1,256>>>(indice);
    prep_weights<<<1024,256>>>(Wih,Whh,bih,bhh,W_w,fc,h0);
    gather_k<<<(int)(((long)NT*KC*(DM/4))/256),256>>>(h_tensor,c_tensor,indice,x,h0,c0);

    // 2) Wx = x @ W_w^T + W_b   (sorted rows, original cols) -> fp32
    gemm_h<<<dim3(GD/128, NT/128, 1),256,SMEM_SZ>>>(
        p_x16,0, p_Wwh,0, W_b,0,
        p_Wx,(__half*)0,0,GD, NT,GD,DM, (const int*)0,0, (const float*)0);

    // 3) the 16-step recurrence: work-queue persistent kernel, 64-wide chunks
    rec_k<<<NCTA,256,SMEM_R>>>();

    // 4) backward one-step for j=1..3: GEMM + fused LSTM gates -> ylcat
    gemm_h<<<dim3(GD/128, NT/128, 3),256,SMEM_SZ>>>(
        p_xlast16,0, p_WihBh,(long)GD*DM, p_hb,(long)GD,
        (float*)0,(__half*)0,0,0, NT,GD,DM, (const int*)0,0, c0);

    // 5) fc projections -> fp16 (ycat0 k-major; skip k>=len)
    gemm_h<<<dim3(DM/128, (NT*KC)/128, 1),256,SMEM_SZ>>>(
        p_ycat016,0, p_fch,0, (const float*)0,0,
        (float*)0,p_ys016,0,DM, NT*KC,DM,2*DM, p_cntF,1, (const float*)0);
    gemm_h<<<dim3(DM/128, NT/128, 3),256,SMEM_SZ>>>(
        p_ylcat16,(long)NT*2*DM, p_fch + (long)DM*2*DM,(long)DM*2*DM,
        (const float*)0,0,
        (float*)0,p_ysl16,(long)NT*DM,DM, NT,DM,2*DM, (const int*)0,0, (const float*)0);

    // 6) final combine -> (new_h, new_c), un-permuted
    final_k<<<NT,DM>>>(out);
}

// round 17
// speedup vs baseline: 1.2076x; 1.2076x over previous
#include <cuda_runtime.h>
#include <cuda_fp16.h>
#include <math.h>
#include <stdint.h>

#define NT   4096      // trees
#define KC   16        // children
#define DM   256       // DOUT
#define GD   1024      // 4*DOUT
#define NCMB 5         // recurrent combos: (j0,f),(j0,b),(j1,f),(j2,f),(j3,f)
#define NCTA 296       // persistent grid: 2 CTAs x 148 SMs

// ---------------- scratch (device globals; no allocations allowed) ----------
__device__ __align__(16) __half s_x16   [(long)NT*DM];
__device__ __align__(16) __half s_xseq16[(long)NT*KC*DM];   // k-major: [k*NT+n][DM]
__device__ __align__(16) __half s_xlast16[(long)NT*DM];
__device__ __align__(16) __half s_Wih5h [(long)NCMB*GD*DM]; // gate-interleaved
__device__ __align__(16) __half s_Whh5h [(long)NCMB*GD*DM]; // gate-interleaved
__device__ __align__(16) __half s_WihBh [3L*GD*DM];         // gate-interleaved
__device__ __align__(16) __half s_Wwh   [(long)GD*DM];
__device__ __align__(16) __half s_fch   [4L*DM*2*DM];
__device__ __align__(16) __half s_h16   [2L*NCMB*NT*DM];    // double-buffered
__device__ __align__(16) __half s_ycat016[(long)NT*KC*2*DM]; // k-major rows
__device__ __align__(16) __half s_ylcat16[3L*NT*2*DM];
__device__ __align__(16) __half s_ys016 [(long)NT*KC*DM];
__device__ __align__(16) __half s_ysl16 [3L*NT*DM];
__device__ float s_cseq [(long)NT*KC*DM];
__device__ int   s_len  [NT];        // sorted (descending)
__device__ int   s_ord  [NT];
__device__ int   s_lenOrig[NT];
__device__ int   s_cntF [17];        // cntF[s] = #trees with len > s
__device__ float s_b5   [NCMB*GD];   // gate-interleaved
__device__ float s_hb   [3*GD];      // gate-interleaved
__device__ float s_c    [(long)NCMB*NT*DM];
__device__ float s_Wx   [(long)NT*GD];
// dependency-queue state (reset each launch in sort_k)
__device__ int s_tileBase[16*NCMB+1];  // cumulative rec tiles per (s,c)
__device__ int s_tileSC [16*NCMB*32*8]; // tile -> segment index (flat decode)
__device__ int s_firstStepB[32];       // bwd combo: first active step per rowTile
__device__ int s_dep[NCMB*32];         // completed col-tiles per (combo,rowTile)
__device__ int g_qHead;

__device__ __forceinline__ float sigf(float x){ return 1.f/(1.f+expf(-x)); }

__device__ __forceinline__ void mma_f16(float4& c,
        uint32_t a0, uint32_t a1, uint32_t a2, uint32_t a3,
        uint32_t b0, uint32_t b1){
    asm volatile(
        "mma.sync.aligned.m16n8k16.row.col.f32.f16.f16.f32 "
        "{%0,%1,%2,%3}, {%4,%5,%6,%7}, {%8,%9}, {%0,%1,%2,%3};"
        : "+f"(c.x), "+f"(c.y), "+f"(c.z), "+f"(c.w)
        : "r"(a0), "r"(a1), "r"(a2), "r"(a3), "r"(b0), "r"(b1));
}

__device__ __forceinline__ void ldsm_x4(uint32_t& r0, uint32_t& r1,
                                        uint32_t& r2, uint32_t& r3, uint32_t addr){
    asm volatile("ldmatrix.sync.aligned.m8n8.x4.shared.b16 {%0,%1,%2,%3}, [%4];"
                 : "=r"(r0),"=r"(r1),"=r"(r2),"=r"(r3) : "r"(addr));
}
__device__ __forceinline__ void ldsm_x2(uint32_t& r0, uint32_t& r1, uint32_t addr){
    asm volatile("ldmatrix.sync.aligned.m8n8.x2.shared.b16 {%0,%1}, [%2];"
                 : "=r"(r0),"=r"(r1) : "r"(addr));
}

// ---------------- sort + queue-table build -----------------------------------
__global__ void sort_k(const int* __restrict__ indice){
    __shared__ int hist[17];
    __shared__ int binCur[17];
    int tid = threadIdx.x;
    if (tid < 17) hist[tid]=0;
    __syncthreads();
    for (int n=tid; n<NT; n+=blockDim.x){
        int l=0;
        #pragma unroll
        for (int k=0;k<KC;k++) if (indice[n*KC+k]!=-1) l++;
        s_lenOrig[n]=l;
        atomicAdd(&hist[l],1);
    }
    __syncthreads();
    if (tid==0){
        int run=0;
        for (int l=16;l>=1;l--){ binCur[l]=run; run+=hist[l]; }
        int c=0;
        s_cntF[16]=0;
        for (int s=15;s>=0;s--){ c += hist[s+1]; s_cntF[s]=c; }
        g_qHead = 0;
        int tb=0; s_tileBase[0]=0;
        for (int i=0;i<16*NCMB;i++){
            int s=i/NCMB, cc=i%NCMB;
            int lim = (cc==1)? s_cntF[15-s] : s_cntF[s];
            tb += ((lim+127)>>7)<<3;
            s_tileBase[i+1]=tb;
        }
        for (int r=0;r<32;r++){
            int fs=16;
            for (int s=0;s<16;s++) if (s_cntF[15-s] > 128*r){ fs=s; break; }
            s_firstStepB[r]=fs;
        }
    }
    if (tid < NCMB*32) s_dep[tid]=0;
    __syncthreads();
    for (int i=0; i<16*NCMB; i++){
        int b0 = s_tileBase[i], b1 = s_tileBase[i+1];
        for (int t = b0 + tid; t < b1; t += blockDim.x) s_tileSC[t] = i;
    }
    for (int n=tid; n<NT; n+=blockDim.x){
        int l=s_lenOrig[n];
        int pos=atomicAdd(&binCur[l],1);
        s_ord[pos]=n;
        s_len[pos]=l;
    }
}

// ---------------- prep: pack + convert weights (gate-interleaved) -----------
__global__ void prep_weights(const float* __restrict__ Wih, const float* __restrict__ Whh,
                             const float* __restrict__ bih, const float* __restrict__ bhh,
                             const float* __restrict__ W_w, const float* __restrict__ fc,
                             const float* __restrict__ h0){
    const int map5[5]={0,1,2,4,6};
    const int mapB[3]={3,5,7};
    long idx = (long)blockIdx.x*blockDim.x + threadIdx.x;
    long stride = (long)gridDim.x*blockDim.x;
    for (long i=idx; i<(long)NCMB*GD*DM; i+=stride){
        int cmb = (int)(i/((long)GD*DM)); long rem = i%((long)GD*DM);
        int rp = (int)(rem/DM); int kcol = (int)(rem%DM);
        int q = (rp>>5)&3; int du = ((rp>>7)<<5)|(rp&31);
        long src = (long)map5[cmb]*GD*DM + (long)(q*256+du)*DM + kcol;
        s_Wih5h[i]=__float2half(Wih[src]);
        s_Whh5h[i]=__float2half(Whh[src]);
    }
    for (long i=idx; i<3L*GD*DM; i+=stride){
        int jb = (int)(i/((long)GD*DM)); long rem = i%((long)GD*DM);
        int rp = (int)(rem/DM); int kcol = (int)(rem%DM);
        int q = (rp>>5)&3; int du = ((rp>>7)<<5)|(rp&31);
        s_WihBh[i]=__float2half(Wih[(long)mapB[jb]*GD*DM + (long)(q*256+du)*DM + kcol]);
    }
    for (long i=idx; i<(long)GD*DM; i+=stride)
        s_Wwh[i]=__float2half(W_w[i]);
    for (long i=idx; i<4L*DM*2*DM; i+=stride)
        s_fch[i]=__float2half(fc[i]);
    for (long i=idx; i<(long)NCMB*GD; i+=stride){
        int cmb=(int)(i/GD); int rp=(int)(i%GD);
        int q=(rp>>5)&3; int du=((rp>>7)<<5)|(rp&31);
        int r = q*256+du;
        s_b5[i]=bih[map5[cmb]*GD+r]+bhh[map5[cmb]*GD+r];
    }
    for (long i=idx; i<3L*GD; i+=stride){
        int jb=(int)(i/GD); int rp=(int)(i%GD);
        int q=(rp>>5)&3; int du=((rp>>7)<<5)|(rp&31);
        int r=q*256+du;
        int jd2=2*(jb+1)+1;
        const float* w = Whh + (long)jd2*GD*DM + (long)r*DM;
        const float* h = h0 + (jb+1)*DM;
        float acc=0.f;
        #pragma unroll 8
        for (int d=0; d<DM; d++) acc += h[d]*w[d];
        s_hb[i] = acc + bih[jd2*GD+r] + bhh[jd2*GD+r];
    }
}

// ------ gather (active children) + x conv + h/c init, one kernel -------------
__global__ void gather_k(const float* __restrict__ h_tensor,
                         const float* __restrict__ c_tensor,
                         const int*   __restrict__ indice,
                         const float* __restrict__ x,
                         const float* __restrict__ h0, const float* __restrict__ c0){
    long idx = (long)blockIdx.x*blockDim.x + threadIdx.x;
    long gsz = (long)gridDim.x*blockDim.x;
    const int jmap[5]={0,0,1,2,3};

    for (long i=idx; i<(long)NT*(DM/4); i+=gsz){
        int sn = (int)(i/(DM/4)); int d4 = (int)(i%(DM/4));
        int orig = s_ord[sn];
        float4 v = ((const float4*)x)[(long)orig*(DM/4)+d4];
        ((__half2*)s_x16)[((long)sn*DM + d4*4)>>1]     = __floats2half2_rn(v.x, v.y);
        ((__half2*)s_x16)[(((long)sn*DM + d4*4)>>1)+1] = __floats2half2_rn(v.z, v.w);
    }
    for (long i=idx; i<(long)NCMB*NT*(DM/2); i+=gsz){
        int cmb = (int)((i/((long)NT*(DM/2)))%NCMB);
        int d2 = (int)(i%(DM/2));
        __half2 v = __floats2half2_rn(h0[jmap[cmb]*DM+2*d2], h0[jmap[cmb]*DM+2*d2+1]);
        ((__half2*)s_h16)[i] = v;
        ((__half2*)s_h16)[i + (long)NCMB*NT*(DM/2)] = v;
    }
    for (long i=idx; i<(long)NCMB*NT*(DM/2); i+=gsz){
        int cmb = (int)(i/((long)NT*(DM/2)));
        int d2 = (int)(i%(DM/2));
        ((float2*)s_c)[i] = make_float2(c0[jmap[cmb]*DM+2*d2], c0[jmap[cmb]*DM+2*d2+1]);
    }
    for (long i=idx; i<(long)NT*KC*(DM/4); i+=gsz){
        long nk = i / (DM/4);
        int  d4 = (int)(i % (DM/4));
        int sn = (int)(nk >> 4); int k = (int)(nk & 15);
        int len = s_len[sn];
        if (k >= len) continue;
        int orig = s_ord[sn];
        int id = indice[orig*KC+k];
        float4 h = ((const float4*)h_tensor)[(long)id*(DM/4)+d4];
        ((float4*)s_cseq)[((long)sn*KC+k)*(DM/4)+d4] = ((const float4*)c_tensor)[(long)id*(DM/4)+d4];
        __half2 h01 = __floats2half2_rn(h.x, h.y);
        __half2 h23 = __floats2half2_rn(h.z, h.w);
        long xo = ((long)k*NT + sn)*DM + d4*4;
        ((__half2*)s_xseq16)[xo>>1]     = h01;
        ((__half2*)s_xseq16)[(xo>>1)+1] = h23;
        if (k == len-1){
            long lo = (long)sn*DM + d4*4;
            ((__half2*)s_xlast16)[lo>>1]     = h01;
            ((__half2*)s_xlast16)[(lo>>1)+1] = h23;
        }
    }
}

// ---------------- shared GEMM plumbing ---------------------------------------
#define STR2 20                       // u32 per smem row (16 data + 4 pad)
#define AB_U32 (128*STR2)
#define ABUF(b) ((b)*AB_U32)
#define BBUF(b) (3*AB_U32 + (b)*AB_U32)
#define SMEM_SZ (6*AB_U32*4)          // 61440 bytes

#define LDSM_OFFSETS()                                                            \
    int aoff[4], boff[4];                                                         \
    {                                                                             \
        int rA = lane & 15;                                                       \
        int cA = (lane >> 4) << 2;                                                \
        _Pragma("unroll")                                                         \
        for (int mt=0; mt<4; mt++)                                                \
            aoff[mt] = ((wrw*64 + mt*16 + rA)*STR2 + cA)*4;                       \
        int rB = lane & 7;                                                        \
        int cB = ((lane >> 3) & 1) << 2;                                          \
        _Pragma("unroll")                                                         \
        for (int nt=0; nt<4; nt++)                                                \
            boff[nt] = ((wcw*32 + nt*8 + rB)*STR2 + cB)*4;                        \
    }

#define PRE16(Ab, Bb, Astride, Bstride, brow_, bcol_, kb_, buf) do {              \
    long kb = (kb_);                                                              \
    _Pragma("unroll")                                                             \
    for (int l=0;l<2;l++){                                                        \
        int r = lrow4 + l*64;                                                     \
        uint32_t da = sbase + (ABUF(buf) + r*STR2)*4 + lq*16;                     \
        asm volatile("cp.async.cg.shared.global [%0],[%1],16;"                    \
                     :: "r"(da), "l"((Ab) + ((brow_)+r)*(Astride) + kb + lq*8));  \
        uint32_t db = sbase + (BBUF(buf) + r*STR2)*4 + lq*16;                     \
        asm volatile("cp.async.cg.shared.global [%0],[%1],16;"                    \
                     :: "r"(db), "l"((Bb) + ((bcol_) + r)*(Bstride) + kb + lq*8)); \
    }                                                                             \
    asm volatile("cp.async.commit_group;");                                       \
} while(0)

#define MAINLOOP_CHUNK(cb)  do {                                                  \
    uint32_t baA = sbase + (ABUF(cb))*4;                                          \
    uint32_t baB = sbase + (BBUF(cb))*4;                                          \
    _Pragma("unroll")                                                             \
    for (int ks = 0; ks < 2; ks++){                                               \
        uint32_t af[4][4], bf[4][2];                                              \
        _Pragma("unroll")                                                         \
        for (int mt=0; mt<4; mt++)                                                \
            ldsm_x4(af[mt][0],af[mt][1],af[mt][2],af[mt][3],                      \
                    baA + ks*32 + aoff[mt]);                                      \
        _Pragma("unroll")                                                         \
        for (int nt=0; nt<4; nt++)                                                \
            ldsm_x2(bf[nt][0],bf[nt][1], baB + ks*32 + boff[nt]);                 \
        _Pragma("unroll")                                                         \
        for (int mt=0; mt<4; mt++)                                                \
            _Pragma("unroll")                                                     \
            for (int nt=0; nt<4; nt++)                                            \
                mma_f16(acc[mt][nt], af[mt][0],af[mt][1],af[mt][2],af[mt][3],     \
                        bf[nt][0], bf[nt][1]);                                    \
    }                                                                             \
} while(0)

// ---------------- generic fp16 GEMM (non-recurrent launches) -----------------
__global__ void __launch_bounds__(256,2) gemm_h(
    const __half* __restrict__ A, long aBatch,
    const __half* __restrict__ B, long bBatch,
    const float* __restrict__ bias, long biasBatch,
    float* __restrict__ CF, __half* __restrict__ CH, long cBatch, int cRow,
    int M, int N, int K,
    const int* __restrict__ exCnt, int exitKind,
    const float* __restrict__ fuseC0)
{
    int z = blockIdx.z;
    long brow = (long)blockIdx.y * 128;
    if (exitKind == 1){
        int k = (int)(brow >> 12);
        int w = (int)(brow & 4095);
        if (w >= exCnt[k]) return;
    }
    extern __shared__ uint32_t sm[];
    uint32_t sbase;
    asm("{ .reg .u64 t; cvta.to.shared.u64 t, %1; cvt.u32.u64 %0, t; }"
        : "=r"(sbase) : "l"(sm));
    int tid = threadIdx.x;
    int wid = tid >> 5, lane = tid & 31;
    int gq = lane >> 2, tq = lane & 3;
    int wrw = wid >> 2, wcw = wid & 3;
    int lrow4 = tid >> 2, lq = tid & 3;
    LDSM_OFFSETS();

    const __half* Ab = A + (long)z*aBatch;
    const __half* Bb = B + (long)z*bBatch;
    long bcol = (long)blockIdx.x * 128;

    float4 acc[4][4];
    #pragma unroll
    for (int i=0;i<4;i++)
        #pragma unroll
        for (int j=0;j<4;j++) acc[i][j] = make_float4(0.f,0.f,0.f,0.f);

    int nCh = K >> 5;
    PRE16(Ab, Bb, K, K, brow, bcol, 0L, 0);
    if (nCh > 1) PRE16(Ab, Bb, K, K, brow, bcol, 32L, 1);
    for (int i = 0; i < nCh; i++){
        if (i + 1 < nCh) asm volatile("cp.async.wait_group 1;" ::: "memory");
        else             asm volatile("cp.async.wait_group 0;" ::: "memory");
        __syncthreads();
        MAINLOOP_CHUNK(i % 3);
        if (i + 2 < nCh){
            PRE16(Ab, Bb, K, K, brow, bcol, (long)(i+2)*32, (i + 2) % 3);
        }
    }

    const float* biasb = bias ? bias + (long)z*biasBatch : (const float*)0;

    if (fuseC0){
        __half* gs = (__half*)sm;
        __syncthreads();
        #pragma unroll
        for (int mt=0; mt<4; mt++){
            int lr0 = wrw*64 + mt*16 + gq;
            #pragma unroll
            for (int nt=0; nt<4; nt++){
                int lcol = wcw*32 + nt*8 + 2*tq;
                long col2 = bcol + lcol;
                float b0 = biasb[col2], b1 = biasb[col2+1];
                *reinterpret_cast<__half2*>(&gs[lr0*132 + lcol]) =
                    __floats2half2_rn(acc[mt][nt].x + b0, acc[mt][nt].y + b1);
                *reinterpret_cast<__half2*>(&gs[(lr0+8)*132 + lcol]) =
                    __floats2half2_rn(acc[mt][nt].z + b0, acc[mt][nt].w + b1);
            }
        }
        __syncthreads();
        int colTile = blockIdx.x;
        #pragma unroll
        for (int it=0; it<8; it++){
            int idx2 = tid + it*256;
            int row = idx2 >> 4, up = idx2 & 15;
            int u = up*2;
            int n = (int)brow + row;
            int d = (colTile<<5) + u;
            float2 gi = __half22float2(*reinterpret_cast<const __half2*>(&gs[row*132 + u]));
            float2 gf = __half22float2(*reinterpret_cast<const __half2*>(&gs[row*132 + 32 + u]));
            float2 gu = __half22float2(*reinterpret_cast<const __half2*>(&gs[row*132 + 64 + u]));
            float2 go = __half22float2(*reinterpret_cast<const __half2*>(&gs[row*132 + 96 + u]));
            float2 cp = *reinterpret_cast<const float2*>(&fuseC0[(z+1)*DM + d]);
            float cnx = sigf(gf.x)*cp.x + sigf(gi.x)*tanhf(gu.x);
            float cny = sigf(gf.y)*cp.y + sigf(gi.y)*tanhf(gu.y);
            float hnx = sigf(go.x)*tanhf(cnx);
            float hny = sigf(go.y)*tanhf(cny);
            *reinterpret_cast<__half2*>(&s_ylcat16[((long)z*NT+n)*(2*DM) + DM + d]) =
                __floats2half2_rn(hnx, hny);
        }
        return;
    }

    #pragma unroll
    for (int mt=0; mt<4; mt++){
        long row0 = brow + wrw*64 + mt*16 + gq;
        #pragma unroll
        for (int nt=0; nt<4; nt++){
            long col = bcol + wcw*32 + nt*8 + 2*tq;
            float2 v0 = make_float2(acc[mt][nt].x, acc[mt][nt].y);
            float2 v1 = make_float2(acc[mt][nt].z, acc[mt][nt].w);
            if (biasb){
                v0.x += biasb[col];   v0.y += biasb[col+1];
                v1.x += biasb[col];   v1.y += biasb[col+1];
            }
            if (CH){
                __half* Cb = CH + (long)z*cBatch;
                *reinterpret_cast<__half2*>(&Cb[row0*cRow + col])     = __floats2half2_rn(v0.x, v0.y);
                *reinterpret_cast<__half2*>(&Cb[(row0+8)*cRow + col]) = __floats2half2_rn(v1.x, v1.y);
            } else {
                float* Cb = CF + (long)z*cBatch;
                *reinterpret_cast<float2*>(&Cb[row0*cRow + col])     = v0;
                *reinterpret_cast<float2*>(&Cb[(row0+8)*cRow + col]) = v1;
            }
        }
    }
}

// -------- persistent recurrence: queue + overlapped dep-wait -------------------
// K-chunk order: 0-7 = xseq[kx]@Wih (dep-free, prefetch overlaps dep spin),
//                8-15 = h@Whh (first touched after the acquire sync).
__global__ void __launch_bounds__(256,2) rec_k(){
    extern __shared__ uint32_t sm[];
    __half* gs = (__half*)sm;          // 128 x 132 fp16 staging
    __shared__ int sh4[4];             // decoded (s,c,r,col)
    uint32_t sbase;
    asm("{ .reg .u64 t; cvta.to.shared.u64 t, %1; cvt.u32.u64 %0, t; }"
        : "=r"(sbase) : "l"(sm));
    int tid = threadIdx.x;
    int wid = tid >> 5, lane = tid & 31;
    int gq = lane >> 2, tq = lane & 3;
    int wrw = wid >> 2, wcw = wid & 3;
    int lrow4 = tid >> 2, lq = tid & 3;
    LDSM_OFFSETS();

    int total = s_tileBase[16*NCMB];

    while (true){
        if (tid == 0){
            int t = atomicAdd(&g_qHead, 1);
            int ss=-1, cc=0, rr=0, col=0;
            if (t < total){
                int i = s_tileSC[t];                 // flat decode: 1 load
                ss = i/NCMB; cc = i%NCMB;
                int off = t - s_tileBase[i];
                rr = off >> 3; col = off & 7;
            }
            sh4[0]=ss; sh4[1]=cc; sh4[2]=rr; sh4[3]=col;
        }
        __syncthreads();
        int s = sh4[0];
        if (s < 0) break;
        int c = sh4[1], rowTile = sh4[2], colTile = sh4[3];
        __syncthreads();            // sh4 consumed before next overwrite

        int rdb = s & 1, wrb = rdb ^ 1;
        int lim = (c==1) ? s_cntF[15-s] : s_cntF[s];
        long brow = (long)rowTile << 7;
        long bcol = (long)colTile << 7;
        const __half* Ah = s_h16 + ((long)rdb*NCMB + c)*NT*DM;
        const __half* Bh = s_Whh5h + (long)c*GD*DM;
        int kx = (c==1) ? 15-s : s;
        const __half* Ax = s_xseq16 + (long)kx*NT*DM;
        const __half* Bx = s_Wih5h + (long)c*GD*DM;
        const float* biasb = s_b5 + c*GD;

        float4 acc[4][4];
        #pragma unroll
        for (int i=0;i<4;i++)
            #pragma unroll
            for (int j=0;j<4;j++) acc[i][j] = make_float4(0.f,0.f,0.f,0.f);

        // chunks 0-7: xseq (dep-free); 8-15: h (dep-guarded)
        #define PRER(ch, buf) do {                                            \
            if ((ch) < 8) PRE16(Ax, Bx, DM, DM, brow, bcol,                   \
                                (long)(ch)*32, buf);                          \
            else          PRE16(Ah, Bh, DM, DM, brow, bcol,                   \
                                (long)((ch)-8)*32, buf);                      \
        } while(0)

        // issue dep-free prefetches, then overlap dep spin with them
        PRER(0, 0);
        PRER(1, 1);
        if (tid == 0){
            int first = (c==1) ? s_firstStepB[rowTile] : 0;
            int need = 8*(s - first);
            if (need > 0){
                while (atomicAdd(&s_dep[c*32+rowTile], 0) < need) __nanosleep(64);
                __threadfence();   // acquire: order dep-read before h reads
            }
        }
        __syncthreads();           // release dep-acquire to all warps

        #pragma unroll
        for (int i = 0; i < 16; i++){
            if (i < 15) asm volatile("cp.async.wait_group 1;" ::: "memory");
            else        asm volatile("cp.async.wait_group 0;" ::: "memory");
            __syncthreads();
            MAINLOOP_CHUNK(i % 3);
            if (i + 2 < 16) PRER(i + 2, (i + 2) % 3);
        }
        #undef PRER
        __syncthreads();   // ring smem free before gs staging

        #pragma unroll
        for (int mt=0; mt<4; mt++){
            int lr0 = wrw*64 + mt*16 + gq;
            #pragma unroll
            for (int nt=0; nt<4; nt++){
                int lcol = wcw*32 + nt*8 + 2*tq;
                long col2 = bcol + lcol;
                float b0 = biasb[col2], b1 = biasb[col2+1];
                *reinterpret_cast<__half2*>(&gs[lr0*132 + lcol]) =
                    __floats2half2_rn(acc[mt][nt].x + b0, acc[mt][nt].y + b1);
                *reinterpret_cast<__half2*>(&gs[(lr0+8)*132 + lcol]) =
                    __floats2half2_rn(acc[mt][nt].z + b0, acc[mt][nt].w + b1);
            }
        }
        __syncthreads();

        #pragma unroll
        for (int it=0; it<8; it++){
            int idx2 = tid + it*256;
            int row = idx2 >> 4, up = idx2 & 15;
            int u = up*2;
            int n = (int)brow + row;
            if (n >= lim) continue;
            int d = (colTile<<5) + u;
            float2 gi = __half22float2(*reinterpret_cast<const __half2*>(&gs[row*132 + u]));
            float2 gf = __half22float2(*reinterpret_cast<const __half2*>(&gs[row*132 + 32 + u]));
            float2 gu = __half22float2(*reinterpret_cast<const __half2*>(&gs[row*132 + 64 + u]));
            float2 go = __half22float2(*reinterpret_cast<const __half2*>(&gs[row*132 + 96 + u]));
            long ist = ((long)c*NT + n)*DM + d;
            float2 cp = *reinterpret_cast<const float2*>(&s_c[ist]);
            float2 cn, hn;
            cn.x = sigf(gf.x)*cp.x + sigf(gi.x)*tanhf(gu.x);
            cn.y = sigf(gf.y)*cp.y + sigf(gi.y)*tanhf(gu.y);
            hn.x = sigf(go.x)*tanhf(cn.x);
            hn.y = sigf(go.y)*tanhf(cn.y);
            *reinterpret_cast<float2*>(&s_c[ist]) = cn;
            __half2 hn2 = __floats2half2_rn(hn.x, hn.y);
            *reinterpret_cast<__half2*>(&s_h16[((long)wrb*NCMB + c)*NT*DM + (long)n*DM + d]) = hn2;
            if (c == 0)
                *reinterpret_cast<__half2*>(&s_ycat016[((long)s*NT+n)*(2*DM) + d]) = hn2;
            else if (c == 1)
                *reinterpret_cast<__half2*>(&s_ycat016[((long)(15-s)*NT+n)*(2*DM) + DM + d]) = hn2;
            else if (s == s_len[n]-1)
                *reinterpret_cast<__half2*>(&s_ylcat16[((long)(c-2)*NT+n)*(2*DM) + d]) = hn2;
        }
        __threadfence();           // publish h/c writes
        __syncthreads();
        if (tid == 0) atomicAdd(&s_dep[c*32+rowTile], 1);
    }
}

__global__ void final_k(float* __restrict__ out){
    int n = blockIdx.x, d = threadIdx.x;   // n = sorted slot
    int orig = s_ord[n];
    float wf = s_Wx[(long)n*GD + d];
    float wi = s_Wx[(long)n*GD + DM + d];
    float wu = s_Wx[(long)n*GD + 2*DM + d];
    float wo = s_Wx[(long)n*GD + 3*DM + d];
    int len = s_len[n];
    float bf = 0.f;
    for (int k=0;k<len;k++){
        float y  = __half2float(s_ys016[((long)k*NT+n)*DM + d]);
        float cc = s_cseq[((long)n*KC+k)*DM + d];
        bf += sigf(wf + y) * cc;
    }
    float bi = sigf (__half2float(s_ysl16[0L*NT*DM + (long)n*DM + d]) + wi);
    float bu = tanhf(__half2float(s_ysl16[1L*NT*DM + (long)n*DM + d]) + wu);
    float bo = sigf (__half2float(s_ysl16[2L*NT*DM + (long)n*DM + d]) + wo);
    float ncv = bi*bu + bf;
    float nhv = bo*tanhf(ncv);
    out[(long)orig*DM + d] = nhv;
    out[(long)NT*DM + (long)orig*DM + d] = ncv;
}

// =============================================================================
extern "C" void kernel_launch(void* const* d_in, const int* in_sizes, int n_in,
                              void* d_out, int out_size) {
    const float* x        = (const float*)d_in[0];
    const float* h_tensor = (const float*)d_in[1];
    const float* c_tensor = (const float*)d_in[2];
    const int*   indice   = (const int*)  d_in[3];
    const float* W_w      = (const float*)d_in[4];
    const float* W_b      = (const float*)d_in[5];
    const float* h0       = (const float*)d_in[6];
    const float* c0       = (const float*)d_in[7];
    const float* Wih      = (const float*)d_in[8];
    const float* Whh      = (const float*)d_in[9];
    const float* bih      = (const float*)d_in[10];
    const float* bhh      = (const float*)d_in[11];
    const float* fc       = (const float*)d_in[12];
    float* out = (float*)d_out;

    __half *p_x16,*p_xlast16,*p_WihBh,*p_Wwh,*p_fch,
           *p_ycat016,*p_ylcat16,*p_ys016,*p_ysl16;
    float *p_hb,*p_Wx;
    int *p_cntF;
    cudaGetSymbolAddress((void**)&p_x16,     s_x16);
    cudaGetSymbolAddress((void**)&p_xlast16, s_xlast16);
    cudaGetSymbolAddress((void**)&p_WihBh,   s_WihBh);
    cudaGetSymbolAddress((void**)&p_Wwh,     s_Wwh);
    cudaGetSymbolAddress((void**)&p_fch,     s_fch);
    cudaGetSymbolAddress((void**)&p_ycat016, s_ycat016);
    cudaGetSymbolAddress((void**)&p_ylcat16, s_ylcat16);
    cudaGetSymbolAddress((void**)&p_ys016,   s_ys016);
    cudaGetSymbolAddress((void**)&p_ysl16,   s_ysl16);
    cudaGetSymbolAddress((void**)&p_hb,      s_hb);
    cudaGetSymbolAddress((void**)&p_Wx,      s_Wx);
    cudaGetSymbolAddress((void**)&p_cntF,    s_cntF);
    (void)in_sizes; (void)n_in; (void)out_size;

    cudaFuncSetAttribute(gemm_h, cudaFuncAttributeMaxDynamicSharedMemorySize, SMEM_SZ);
    cudaFuncSetAttribute(rec_k,  cudaFuncAttributeMaxDynamicSharedMemorySize, SMEM_SZ);

    // 1) sort + queue tables, pack/convert weights (+hb), init+gather (merged)
    sort_k<<<1,256>>>(indice);
    prep_weights<<<1024,256>>>(Wih,Whh,bih,bhh,W_w,fc,h0);
    gather_k<<<(int)(((long)NT*KC*(DM/4))/256),256>>>(h_tensor,c_tensor,indice,x,h0,c0);

    // 2) Wx = x @ W_w^T + W_b   (sorted rows, original cols) -> fp32
    gemm_h<<<dim3(GD/128, NT/128, 1),256,SMEM_SZ>>>(
        p_x16,0, p_Wwh,0, W_b,0,
        p_Wx,(__half*)0,0,GD, NT,GD,DM, (const int*)0,0, (const float*)0);

    // 3) the 16-step recurrence: work-queue persistent kernel
    rec_k<<<NCTA,256,SMEM_SZ>>>();

    // 4) backward one-step for j=1..3: GEMM + fused LSTM gates -> ylcat
    gemm_h<<<dim3(GD/128, NT/128, 3),256,SMEM_SZ>>>(
        p_xlast16,0, p_WihBh,(long)GD*DM, p_hb,(long)GD,
        (float*)0,(__half*)0,0,0, NT,GD,DM, (const int*)0,0, c0);

    // 5) fc projections -> fp16 (ycat0 k-major; skip k>=len)
    gemm_h<<<dim3(DM/128, (NT*KC)/128, 1),256,SMEM_SZ>>>(
        p_ycat016,0, p_fch,0, (const float*)0,0,
        (float*)0,p_ys016,0,DM, NT*KC,DM,2*DM, p_cntF,1, (const float*)0);
    gemm_h<<<dim3(DM/128, NT/128, 3),256,SMEM_SZ>>>(
        p_ylcat16,(long)NT*2*DM, p_fch + (long)DM*2*DM,(long)DM*2*DM,
        (const float*)0,0,
        (float*)0,p_ysl16,(long)NT*DM,DM, NT,DM,2*DM, (const int*)0,0, (const float*)0);

    // 6) final combine -> (new_h, new_c), un-permuted
    final_k<<<NT,DM>>>(out);
}